// round 16
// baseline (speedup 1.0000x reference)
#include <cuda_runtime.h>
#include <cstdint>
#include <math_constants.h>

// Problem constants
constexpr int Bb  = 2;
constexpr int Cc  = 128;
constexpr int Nn  = 50000;
constexpr int Mm  = Bb * Nn;
constexpr int Hh  = 2;
constexpr int FHh = 64;
constexpr int OUT = Hh * FHh; // 128
constexpr int Ee  = 800000;

constexpr float NEG_SLOPE_GAT = 0.2f;
constexpr float NEG_SLOPE_ACT = 0.01f;
constexpr float LN_EPS = 1e-5f;
constexpr float SOFTMAX_EPS = 1e-16f;

// Fused count+scan config: 98 blocks x 1024 threads; all co-resident
// (98 < 148 SMs, 1024 thr <= half SM capacity) -> grid barrier is safe.
constexpr int CSR_T      = 1024;
constexpr int CSR_BLOCKS = (Mm + CSR_T - 1) / CSR_T;   // 98
constexpr int CSR_NTHR   = CSR_BLOCKS * CSR_T;         // 100352

// GEMM tiling
constexpr int BM = 128, BK = 32;
constexpr int KSTAGES   = Cc / BK;        // 4
constexpr int NBUF      = 3;              // smem ring (1 sync/stage)
constexpr int TSTRIDE   = BM + 8;         // 136 words: conflict-free frags
constexpr int TILE_WORDS = BK * TSTRIDE;  // 4352
constexpr int TILE_BYTES = TILE_WORDS * 4;            // 17408
constexpr int GEMM_SMEM  = NBUF * 2 * TILE_BYTES;     // 104448 B

// Scratch (device globals: allocation-free)
__device__ float  g_hl[(size_t)Mm * OUT];
__device__ float  g_hr[(size_t)Mm * OUT];
__device__ int    g_deg[Mm];             // zero at static init; self-reset each run
__device__ int    g_rowptr[Mm + 1];
__device__ int    g_cursor[Mm];
__device__ int    g_csr_src[Ee];
__device__ int    g_blocksum[CSR_BLOCKS];

// software grid barrier state
__device__ unsigned          g_bar_cnt = 0;
__device__ volatile unsigned g_bar_gen = 0;

__global__ void __launch_bounds__(256, 2) k_gemm_tc(const float*, const float*,
                                                    const float*, const float*,
                                                    const float*);

namespace {
struct AttrInit {
    AttrInit() {
        cudaFuncSetAttribute(k_gemm_tc,
                             cudaFuncAttributeMaxDynamicSharedMemorySize,
                             GEMM_SMEM);
    }
};
AttrInit g_attr_init;
}

__device__ __forceinline__ void cp_async16(uint32_t dst, const void* src, int sz) {
    asm volatile("cp.async.cg.shared.global [%0], [%1], 16, %2;\n"
                 :: "r"(dst), "l"(src), "r"(sz));
}
__device__ __forceinline__ void cp_commit() {
    asm volatile("cp.async.commit_group;\n");
}
template <int N>
__device__ __forceinline__ void cp_wait() {
    asm volatile("cp.async.wait_group %0;\n" :: "n"(N));
}

// ---- software grid barrier (all CSR_BLOCKS co-resident by construction) ----
__device__ __forceinline__ void gsync() {
    __syncthreads();
    if (threadIdx.x == 0) {
        unsigned gen = g_bar_gen;
        __threadfence();                       // release prior writes
        unsigned arrived = atomicAdd(&g_bar_cnt, 1u);
        if (arrived == CSR_BLOCKS - 1) {
            g_bar_cnt = 0;
            __threadfence();
            g_bar_gen = gen + 1;               // release
        } else {
            while (g_bar_gen == gen) __nanosleep(64);
        }
        __threadfence();                       // acquire
    }
    __syncthreads();
}

// ---- K_CSR_A: fused count + block sums + scan (one launch, 2 grid barriers).
// g_deg is zero on entry (static init / previous run's self-reset).
__global__ void __launch_bounds__(CSR_T)
k_csr_a(const int* __restrict__ ei) {
    __shared__ int wsum[32];
    __shared__ int boff_sh;
    int t = threadIdx.x, b = blockIdx.x;
    int gtid = b * CSR_T + t;

    // Phase 1: degree count, int4 chunks, grid-stride (Ee % 4 == 0)
    for (int c = gtid; c < Ee / 4; c += CSR_NTHR) {
        int4 d4 = *(const int4*)(ei + Ee + c * 4);
        atomicAdd(&g_deg[d4.x], 1);
        atomicAdd(&g_deg[d4.y], 1);
        atomicAdd(&g_deg[d4.z], 1);
        atomicAdd(&g_deg[d4.w], 1);
    }
    gsync();

    // Phase 2: per-block degree sums
    int v = (gtid < Mm) ? g_deg[gtid] : 0;
    {
        int s = v;
        #pragma unroll
        for (int off = 16; off > 0; off >>= 1)
            s += __shfl_xor_sync(0xFFFFFFFFu, s, off);
        if ((t & 31) == 0) wsum[t >> 5] = s;
        __syncthreads();
        if (t < 32) {
            int ws = wsum[t];
            #pragma unroll
            for (int off = 16; off > 0; off >>= 1)
                ws += __shfl_xor_sync(0xFFFFFFFFu, ws, off);
            if (t == 0) g_blocksum[b] = ws;
        }
    }
    gsync();

    // Phase 3: block exclusive scan + block offset -> rowptr/cursor; reset deg.
    {
        int lane = t & 31, w = t >> 5;
        int s = v;
        #pragma unroll
        for (int off = 1; off < 32; off <<= 1) {
            int x = __shfl_up_sync(0xFFFFFFFFu, s, off);
            if (lane >= off) s += x;
        }
        if (lane == 31) wsum[w] = s;
        __syncthreads();
        if (t < 32) {
            int ws = wsum[t];
            #pragma unroll
            for (int off = 1; off < 32; off <<= 1) {
                int x = __shfl_up_sync(0xFFFFFFFFu, ws, off);
                if (t >= off) ws += x;
            }
            wsum[t] = ws;
            int acc = 0;
            for (int j = t; j < b; j += 32) acc += g_blocksum[j];
            #pragma unroll
            for (int off = 16; off > 0; off >>= 1)
                acc += __shfl_xor_sync(0xFFFFFFFFu, acc, off);
            if (t == 0) boff_sh = acc;
        }
        __syncthreads();
        int boff = boff_sh;
        int woff = (w == 0) ? 0 : wsum[w - 1];
        if (gtid < Mm) {
            int rp = (s - v) + woff + boff;
            g_rowptr[gtid] = rp;
            g_cursor[gtid] = rp;
            g_deg[gtid]    = 0;     // self-reset for next run
        }
        if (b == CSR_BLOCKS - 1 && t == 0)
            g_rowptr[Mm] = boff + g_blocksum[b];
    }
}

// ---- K_SCATTER: wide grid (full atomic throughput), int4 chunks ----
__global__ void k_scatter(const int* __restrict__ ei) {
    int t = blockIdx.x * blockDim.x + threadIdx.x;
    int e4 = t * 4;
    if (e4 + 4 <= Ee) {
        int4 s4 = *(const int4*)(ei + e4);
        int4 d4 = *(const int4*)(ei + Ee + e4);
        g_csr_src[atomicAdd(&g_cursor[d4.x], 1)] = s4.x;
        g_csr_src[atomicAdd(&g_cursor[d4.y], 1)] = s4.y;
        g_csr_src[atomicAdd(&g_cursor[d4.z], 1)] = s4.z;
        g_csr_src[atomicAdd(&g_cursor[d4.w], 1)] = s4.w;
    } else {
        for (int e = e4; e < Ee; e++)
            g_csr_src[atomicAdd(&g_cursor[ei[Ee + e]], 1)] = ei[e];
    }
}

// ---- K_GEMM: dual GEMM, cp.async 3-stage ring, raw-fp32 tf32 mma ----
__global__ void __launch_bounds__(256, 2)
k_gemm_tc(const float* __restrict__ x,
          const float* __restrict__ Wl, const float* __restrict__ bl,
          const float* __restrict__ Wr, const float* __restrict__ br) {
    extern __shared__ uint32_t smem_dyn[];
    const float* W    = blockIdx.x ? Wr : Wl;
    const float* bias = blockIdx.x ? br : bl;
    float* h          = blockIdx.x ? g_hr : g_hl;

    uint32_t sbase;
    asm("{ .reg .u64 t; cvta.to.shared.u64 t, %1; cvt.u32.u64 %0, t; }"
        : "=r"(sbase) : "l"(smem_dyn));

    int tid  = threadIdx.x;
    int lane = tid & 31;
    int wid  = tid >> 5;
    int wm   = wid & 3;
    int wn   = wid >> 2;
    int lrow = lane >> 2;
    int lcol = lane & 3;

    int m0 = blockIdx.y * BM;

    float acc[2][8][4];
    #pragma unroll
    for (int mt = 0; mt < 2; mt++)
        #pragma unroll
        for (int nt = 0; nt < 8; nt++)
            #pragma unroll
            for (int q = 0; q < 4; q++) acc[mt][nt][q] = 0.f;

    auto stage_copy = [&](int s) {
        int k0 = s * BK;
        uint32_t abase = sbase + (uint32_t)(s % NBUF) * 2 * TILE_BYTES;
        uint32_t bbase = abase + TILE_BYTES;
        #pragma unroll
        for (int i = 0; i < 4; i++) {
            int c    = tid + i * 256;
            int k    = c >> 5;
            int loc  = (c & 31) * 4;
            int mg    = m0 + loc;
            int valid = (mg < Mm) ? 16 : 0;
            int bb    = (mg >= Nn) ? 1 : 0;
            const float* asrc = valid
                ? x + (size_t)bb * Cc * Nn + (size_t)(k0 + k) * Nn + (mg - bb * Nn)
                : x;
            cp_async16(abase + (uint32_t)(k * TSTRIDE + loc) * 4, asrc, valid);
            const float* bsrc = W + (size_t)(k0 + k) * OUT + loc;
            cp_async16(bbase + (uint32_t)(k * TSTRIDE + loc) * 4, bsrc, 16);
        }
        cp_commit();
    };

    stage_copy(0);
    stage_copy(1);

    for (int s = 0; s < KSTAGES; s++) {
        if (s < KSTAGES - 1) cp_wait<1>(); else cp_wait<0>();
        __syncthreads();
        if (s + 2 < KSTAGES) stage_copy(s + 2);

        const uint32_t* A  = smem_dyn + (size_t)(s % NBUF) * 2 * TILE_WORDS;
        const uint32_t* Bt = A + TILE_WORDS;

        #pragma unroll
        for (int kk = 0; kk < 4; kk++) {
            int kb = kk * 8;
            uint32_t af[2][4];
            #pragma unroll
            for (int mt = 0; mt < 2; mt++) {
                int r = wm * 32 + mt * 16 + lrow;
                af[mt][0] = A[(kb + lcol) * TSTRIDE + r];
                af[mt][1] = A[(kb + lcol) * TSTRIDE + r + 8];
                af[mt][2] = A[(kb + lcol + 4) * TSTRIDE + r];
                af[mt][3] = A[(kb + lcol + 4) * TSTRIDE + r + 8];
            }
            #pragma unroll
            for (int nt = 0; nt < 8; nt++) {
                int cn = wn * 64 + nt * 8 + lrow;
                uint32_t b0 = Bt[(kb + lcol) * TSTRIDE + cn];
                uint32_t b1 = Bt[(kb + lcol + 4) * TSTRIDE + cn];
                #pragma unroll
                for (int mt = 0; mt < 2; mt++) {
                    asm volatile(
                        "mma.sync.aligned.m16n8k8.row.col.f32.tf32.tf32.f32 "
                        "{%0,%1,%2,%3}, {%4,%5,%6,%7}, {%8,%9}, {%0,%1,%2,%3};\n"
                        : "+f"(acc[mt][nt][0]), "+f"(acc[mt][nt][1]),
                          "+f"(acc[mt][nt][2]), "+f"(acc[mt][nt][3])
                        : "r"(af[mt][0]), "r"(af[mt][1]), "r"(af[mt][2]), "r"(af[mt][3]),
                          "r"(b0), "r"(b1));
                }
            }
        }
    }

    #pragma unroll
    for (int mt = 0; mt < 2; mt++) {
        #pragma unroll
        for (int nt = 0; nt < 8; nt++) {
            int row = m0 + wm * 32 + mt * 16 + lrow;
            int col = wn * 64 + nt * 8 + lcol * 2;
            float bcol0 = bias[col], bcol1 = bias[col + 1];
            if (row < Mm) {
                float2 v = {acc[mt][nt][0] + bcol0, acc[mt][nt][1] + bcol1};
                *(float2*)&h[(size_t)row * OUT + col] = v;
            }
            if (row + 8 < Mm) {
                float2 v = {acc[mt][nt][2] + bcol0, acc[mt][nt][3] + bcol1};
                *(float2*)&h[(size_t)(row + 8) * OUT + col] = v;
            }
        }
    }
}

// ---- K_GATHER: half-warp-per-edge fused scoring + exp-sum + bias + LN + act ----
// One warp per dst node. Lanes 0-15 process even edges, 16-31 odd edges.
// Each lane owns 8 features: fl = (lane&15)*8. Head0 = lanes (&15) 0-7,
// head1 = lanes (&15) 8-15, so the 3-shuffle logit reduce (xor 4,2,1) stays
// within a head and serves BOTH edges in one instruction stream.
__global__ void __launch_bounds__(256)
k_gather(float* __restrict__ out, const float* __restrict__ att,
         const float* __restrict__ bias,
         const float* __restrict__ gamma, const float* __restrict__ beta) {
    int gid  = blockIdx.x * blockDim.x + threadIdx.x;
    int m    = gid >> 5;
    int lane = threadIdx.x & 31;
    if (m >= Mm) return;
    int start = g_rowptr[m];
    int deg   = g_rowptr[m + 1] - start;

    int half = lane >> 4;          // 0: even edges, 1: odd edges
    int fl   = (lane & 15) * 8;    // this lane's 8-feature base

    const float4 hrA = *(const float4*)(g_hr + (size_t)m * OUT + fl);
    const float4 hrB = *(const float4*)(g_hr + (size_t)m * OUT + fl + 4);
    const float4 atA = *(const float4*)(att + fl);
    const float4 atB = *(const float4*)(att + fl + 4);

    float den = 0.f;
    float ac0 = 0.f, ac1 = 0.f, ac2 = 0.f, ac3 = 0.f;
    float ac4 = 0.f, ac5 = 0.f, ac6 = 0.f, ac7 = 0.f;

    for (int base = 0; base < deg; base += 32) {
        int nb = deg - base; if (nb > 32) nb = 32;
        int sidx = g_csr_src[start + base + ((lane < nb) ? lane : 0)];
        for (int jj = 0; jj < nb; jj += 2) {
            int  eidx = jj + half;
            bool val  = eidx < nb;
            int  s    = __shfl_sync(0xFFFFFFFFu, sidx, val ? eidx : 0);
            const float* lp = g_hl + (size_t)s * OUT + fl;
            const float4 la = *(const float4*)lp;
            const float4 lb = *(const float4*)(lp + 4);
            // logit partial over this lane's 8 features
            float e0 = la.x + hrA.x, e1 = la.y + hrA.y, e2 = la.z + hrA.z, e3 = la.w + hrA.w;
            float e4 = lb.x + hrB.x, e5 = lb.y + hrB.y, e6 = lb.z + hrB.z, e7 = lb.w + hrB.w;
            e0 = e0 > 0.f ? e0 : NEG_SLOPE_GAT * e0;
            e1 = e1 > 0.f ? e1 : NEG_SLOPE_GAT * e1;
            e2 = e2 > 0.f ? e2 : NEG_SLOPE_GAT * e2;
            e3 = e3 > 0.f ? e3 : NEG_SLOPE_GAT * e3;
            e4 = e4 > 0.f ? e4 : NEG_SLOPE_GAT * e4;
            e5 = e5 > 0.f ? e5 : NEG_SLOPE_GAT * e5;
            e6 = e6 > 0.f ? e6 : NEG_SLOPE_GAT * e6;
            e7 = e7 > 0.f ? e7 : NEG_SLOPE_GAT * e7;
            float p = e0 * atA.x + e1 * atA.y + e2 * atA.z + e3 * atA.w
                    + e4 * atB.x + e5 * atB.y + e6 * atB.z + e7 * atB.w;
            // reduce over the 8 lanes of this head (both edges at once)
            p += __shfl_xor_sync(0xFFFFFFFFu, p, 4);
            p += __shfl_xor_sync(0xFFFFFFFFu, p, 2);
            p += __shfl_xor_sync(0xFFFFFFFFu, p, 1);
            float w = val ? __expf(p) : 0.f;
            den += w;
            ac0 += w * la.x; ac1 += w * la.y; ac2 += w * la.z; ac3 += w * la.w;
            ac4 += w * lb.x; ac5 += w * lb.y; ac6 += w * lb.z; ac7 += w * lb.w;
        }
    }

    // merge the two half-warp streams (same features live at lane^16)
    den += __shfl_xor_sync(0xFFFFFFFFu, den, 16);
    ac0 += __shfl_xor_sync(0xFFFFFFFFu, ac0, 16);
    ac1 += __shfl_xor_sync(0xFFFFFFFFu, ac1, 16);
    ac2 += __shfl_xor_sync(0xFFFFFFFFu, ac2, 16);
    ac3 += __shfl_xor_sync(0xFFFFFFFFu, ac3, 16);
    ac4 += __shfl_xor_sync(0xFFFFFFFFu, ac4, 16);
    ac5 += __shfl_xor_sync(0xFFFFFFFFu, ac5, 16);
    ac6 += __shfl_xor_sync(0xFFFFFFFFu, ac6, 16);
    ac7 += __shfl_xor_sync(0xFFFFFFFFu, ac7, 16);

    float inv_d = 1.f / (den + SOFTMAX_EPS);
    const float4 b4a = *(const float4*)(bias + fl);
    const float4 b4b = *(const float4*)(bias + fl + 4);
    float v0 = ac0 * inv_d + b4a.x, v1 = ac1 * inv_d + b4a.y;
    float v2 = ac2 * inv_d + b4a.z, v3 = ac3 * inv_d + b4a.w;
    float v4 = ac4 * inv_d + b4b.x, v5 = ac5 * inv_d + b4b.y;
    float v6 = ac6 * inv_d + b4b.z, v7 = ac7 * inv_d + b4b.w;

    // LN stats: each 16-lane half holds all 128 features -> reduce within 16
    float s  = v0 + v1 + v2 + v3 + v4 + v5 + v6 + v7;
    float s2 = v0 * v0 + v1 * v1 + v2 * v2 + v3 * v3
             + v4 * v4 + v5 * v5 + v6 * v6 + v7 * v7;
    #pragma unroll
    for (int off = 8; off > 0; off >>= 1) {
        s  += __shfl_xor_sync(0xFFFFFFFFu, s,  off);
        s2 += __shfl_xor_sync(0xFFFFFFFFu, s2, off);
    }
    float mu  = s * (1.f / OUT);
    float var = s2 * (1.f / OUT) - mu * mu;
    float inv = rsqrtf(var + LN_EPS);

    const float4 g4a = *(const float4*)(gamma + fl);
    const float4 g4b = *(const float4*)(gamma + fl + 4);
    const float4 t4a = *(const float4*)(beta + fl);
    const float4 t4b = *(const float4*)(beta + fl + 4);
    float4 ya, yb;
    ya.x = (v0 - mu) * inv * g4a.x + t4a.x;
    ya.y = (v1 - mu) * inv * g4a.y + t4a.y;
    ya.z = (v2 - mu) * inv * g4a.z + t4a.z;
    ya.w = (v3 - mu) * inv * g4a.w + t4a.w;
    yb.x = (v4 - mu) * inv * g4b.x + t4b.x;
    yb.y = (v5 - mu) * inv * g4b.y + t4b.y;
    yb.z = (v6 - mu) * inv * g4b.z + t4b.z;
    yb.w = (v7 - mu) * inv * g4b.w + t4b.w;
    ya.x = ya.x > 0.f ? ya.x : NEG_SLOPE_ACT * ya.x;
    ya.y = ya.y > 0.f ? ya.y : NEG_SLOPE_ACT * ya.y;
    ya.z = ya.z > 0.f ? ya.z : NEG_SLOPE_ACT * ya.z;
    ya.w = ya.w > 0.f ? ya.w : NEG_SLOPE_ACT * ya.w;
    yb.x = yb.x > 0.f ? yb.x : NEG_SLOPE_ACT * yb.x;
    yb.y = yb.y > 0.f ? yb.y : NEG_SLOPE_ACT * yb.y;
    yb.z = yb.z > 0.f ? yb.z : NEG_SLOPE_ACT * yb.z;
    yb.w = yb.w > 0.f ? yb.w : NEG_SLOPE_ACT * yb.w;

    if (half == 0) {
        float* op = out + (size_t)m * OUT + fl;
        *(float4*)op       = ya;
        *(float4*)(op + 4) = yb;
    }
}

extern "C" void kernel_launch(void* const* d_in, const int* in_sizes, int n_in,
                              void* d_out, int out_size) {
    const float* x        = (const float*)d_in[0];
    const int*   ei       = (const int*)  d_in[1];
    const float* Wl       = (const float*)d_in[2];
    const float* bl       = (const float*)d_in[3];
    const float* Wr       = (const float*)d_in[4];
    const float* br       = (const float*)d_in[5];
    const float* att      = (const float*)d_in[6];
    const float* bias_gat = (const float*)d_in[7];
    const float* gamma    = (const float*)d_in[8];
    const float* beta     = (const float*)d_in[9];
    float* out = (float*)d_out;

    (void)in_sizes; (void)n_in; (void)out_size;

    // 4 launches, serial on stream 0. k_gather is launch #4 (profiled).
    k_csr_a  <<<CSR_BLOCKS, CSR_T>>>(ei);                     // launch #1
    k_scatter<<<(Ee / 4 + 255) / 256, 256>>>(ei);             // launch #2

    dim3 ggrid(2, (Mm + BM - 1) / BM);
    k_gemm_tc<<<ggrid, 256, GEMM_SMEM>>>(x, Wl, bl, Wr, br);  // launch #3

    k_gather<<<(Mm * 32 + 255) / 256, 256>>>(out, att, bias_gat, gamma, beta); // #4
}

// round 17
// speedup vs baseline: 1.0514x; 1.0514x over previous
#include <cuda_runtime.h>
#include <cstdint>
#include <math_constants.h>

// Problem constants
constexpr int Bb  = 2;
constexpr int Cc  = 128;
constexpr int Nn  = 50000;
constexpr int Mm  = Bb * Nn;
constexpr int Hh  = 2;
constexpr int FHh = 64;
constexpr int OUT = Hh * FHh; // 128
constexpr int Ee  = 800000;

constexpr float NEG_SLOPE_GAT = 0.2f;
constexpr float NEG_SLOPE_ACT = 0.01f;
constexpr float LN_EPS = 1e-5f;
constexpr float SOFTMAX_EPS = 1e-16f;

// Fused count+scan config: 98 blocks x 1024 threads; all co-resident
// (98 < 148 SMs, 1024 thr <= half SM capacity) -> grid barrier is safe.
constexpr int CSR_T      = 1024;
constexpr int CSR_BLOCKS = (Mm + CSR_T - 1) / CSR_T;   // 98
constexpr int CSR_NTHR   = CSR_BLOCKS * CSR_T;         // 100352

// GEMM tiling
constexpr int BM = 128, BK = 32;
constexpr int KSTAGES   = Cc / BK;        // 4
constexpr int NBUF      = 3;              // smem ring (1 sync/stage)
constexpr int TSTRIDE   = BM + 8;         // 136 words: conflict-free frags
constexpr int TILE_WORDS = BK * TSTRIDE;  // 4352
constexpr int TILE_BYTES = TILE_WORDS * 4;            // 17408
constexpr int GEMM_SMEM  = NBUF * 2 * TILE_BYTES;     // 104448 B

// Scratch (device globals: allocation-free)
__device__ float  g_hl[(size_t)Mm * OUT];
__device__ float  g_hr[(size_t)Mm * OUT];
__device__ int    g_deg[Mm];             // zero at static init; self-reset each run
__device__ int    g_rowptr[Mm + 1];
__device__ int    g_cursor[Mm];
__device__ int    g_csr_src[Ee];
__device__ int    g_blocksum[CSR_BLOCKS];

// software grid barrier state
__device__ unsigned          g_bar_cnt = 0;
__device__ volatile unsigned g_bar_gen = 0;

__global__ void __launch_bounds__(256, 2) k_gemm_tc(const float*, const float*,
                                                    const float*, const float*,
                                                    const float*);

namespace {
struct AttrInit {
    AttrInit() {
        cudaFuncSetAttribute(k_gemm_tc,
                             cudaFuncAttributeMaxDynamicSharedMemorySize,
                             GEMM_SMEM);
    }
};
AttrInit g_attr_init;
}

__device__ __forceinline__ void cp_async16(uint32_t dst, const void* src, int sz) {
    asm volatile("cp.async.cg.shared.global [%0], [%1], 16, %2;\n"
                 :: "r"(dst), "l"(src), "r"(sz));
}
__device__ __forceinline__ void cp_commit() {
    asm volatile("cp.async.commit_group;\n");
}
template <int N>
__device__ __forceinline__ void cp_wait() {
    asm volatile("cp.async.wait_group %0;\n" :: "n"(N));
}

// ---- software grid barrier (all CSR_BLOCKS co-resident by construction) ----
__device__ __forceinline__ void gsync() {
    __syncthreads();
    if (threadIdx.x == 0) {
        unsigned gen = g_bar_gen;
        __threadfence();                       // release prior writes
        unsigned arrived = atomicAdd(&g_bar_cnt, 1u);
        if (arrived == CSR_BLOCKS - 1) {
            g_bar_cnt = 0;
            __threadfence();
            g_bar_gen = gen + 1;               // release
        } else {
            while (g_bar_gen == gen) __nanosleep(64);
        }
        __threadfence();                       // acquire
    }
    __syncthreads();
}

// ---- K_CSR_A: fused count + block sums + scan (one launch, 2 grid barriers).
// g_deg is zero on entry (static init / previous run's self-reset).
__global__ void __launch_bounds__(CSR_T)
k_csr_a(const int* __restrict__ ei) {
    __shared__ int wsum[32];
    __shared__ int boff_sh;
    int t = threadIdx.x, b = blockIdx.x;
    int gtid = b * CSR_T + t;

    // Phase 1: degree count, int4 chunks, grid-stride (Ee % 4 == 0)
    for (int c = gtid; c < Ee / 4; c += CSR_NTHR) {
        int4 d4 = *(const int4*)(ei + Ee + c * 4);
        atomicAdd(&g_deg[d4.x], 1);
        atomicAdd(&g_deg[d4.y], 1);
        atomicAdd(&g_deg[d4.z], 1);
        atomicAdd(&g_deg[d4.w], 1);
    }
    gsync();

    // Phase 2: per-block degree sums
    int v = (gtid < Mm) ? g_deg[gtid] : 0;
    {
        int s = v;
        #pragma unroll
        for (int off = 16; off > 0; off >>= 1)
            s += __shfl_xor_sync(0xFFFFFFFFu, s, off);
        if ((t & 31) == 0) wsum[t >> 5] = s;
        __syncthreads();
        if (t < 32) {
            int ws = wsum[t];
            #pragma unroll
            for (int off = 16; off > 0; off >>= 1)
                ws += __shfl_xor_sync(0xFFFFFFFFu, ws, off);
            if (t == 0) g_blocksum[b] = ws;
        }
    }
    gsync();

    // Phase 3: block exclusive scan + block offset -> rowptr/cursor; reset deg.
    {
        int lane = t & 31, w = t >> 5;
        int s = v;
        #pragma unroll
        for (int off = 1; off < 32; off <<= 1) {
            int x = __shfl_up_sync(0xFFFFFFFFu, s, off);
            if (lane >= off) s += x;
        }
        if (lane == 31) wsum[w] = s;
        __syncthreads();
        if (t < 32) {
            int ws = wsum[t];
            #pragma unroll
            for (int off = 1; off < 32; off <<= 1) {
                int x = __shfl_up_sync(0xFFFFFFFFu, ws, off);
                if (t >= off) ws += x;
            }
            wsum[t] = ws;
            int acc = 0;
            for (int j = t; j < b; j += 32) acc += g_blocksum[j];
            #pragma unroll
            for (int off = 16; off > 0; off >>= 1)
                acc += __shfl_xor_sync(0xFFFFFFFFu, acc, off);
            if (t == 0) boff_sh = acc;
        }
        __syncthreads();
        int boff = boff_sh;
        int woff = (w == 0) ? 0 : wsum[w - 1];
        if (gtid < Mm) {
            int rp = (s - v) + woff + boff;
            g_rowptr[gtid] = rp;
            g_cursor[gtid] = rp;
            g_deg[gtid]    = 0;     // self-reset for next run
        }
        if (b == CSR_BLOCKS - 1 && t == 0)
            g_rowptr[Mm] = boff + g_blocksum[b];
    }
}

// ---- K_SCATTER: wide grid (full atomic throughput), int4 chunks ----
__global__ void k_scatter(const int* __restrict__ ei) {
    int t = blockIdx.x * blockDim.x + threadIdx.x;
    int e4 = t * 4;
    if (e4 + 4 <= Ee) {
        int4 s4 = *(const int4*)(ei + e4);
        int4 d4 = *(const int4*)(ei + Ee + e4);
        g_csr_src[atomicAdd(&g_cursor[d4.x], 1)] = s4.x;
        g_csr_src[atomicAdd(&g_cursor[d4.y], 1)] = s4.y;
        g_csr_src[atomicAdd(&g_cursor[d4.z], 1)] = s4.z;
        g_csr_src[atomicAdd(&g_cursor[d4.w], 1)] = s4.w;
    } else {
        for (int e = e4; e < Ee; e++)
            g_csr_src[atomicAdd(&g_cursor[ei[Ee + e]], 1)] = ei[e];
    }
}

// ---- K_GEMM: dual GEMM, cp.async 3-stage ring, raw-fp32 tf32 mma ----
__global__ void __launch_bounds__(256, 2)
k_gemm_tc(const float* __restrict__ x,
          const float* __restrict__ Wl, const float* __restrict__ bl,
          const float* __restrict__ Wr, const float* __restrict__ br) {
    extern __shared__ uint32_t smem_dyn[];
    const float* W    = blockIdx.x ? Wr : Wl;
    const float* bias = blockIdx.x ? br : bl;
    float* h          = blockIdx.x ? g_hr : g_hl;

    uint32_t sbase;
    asm("{ .reg .u64 t; cvta.to.shared.u64 t, %1; cvt.u32.u64 %0, t; }"
        : "=r"(sbase) : "l"(smem_dyn));

    int tid  = threadIdx.x;
    int lane = tid & 31;
    int wid  = tid >> 5;
    int wm   = wid & 3;
    int wn   = wid >> 2;
    int lrow = lane >> 2;
    int lcol = lane & 3;

    int m0 = blockIdx.y * BM;

    float acc[2][8][4];
    #pragma unroll
    for (int mt = 0; mt < 2; mt++)
        #pragma unroll
        for (int nt = 0; nt < 8; nt++)
            #pragma unroll
            for (int q = 0; q < 4; q++) acc[mt][nt][q] = 0.f;

    auto stage_copy = [&](int s) {
        int k0 = s * BK;
        uint32_t abase = sbase + (uint32_t)(s % NBUF) * 2 * TILE_BYTES;
        uint32_t bbase = abase + TILE_BYTES;
        #pragma unroll
        for (int i = 0; i < 4; i++) {
            int c    = tid + i * 256;
            int k    = c >> 5;
            int loc  = (c & 31) * 4;
            int mg    = m0 + loc;
            int valid = (mg < Mm) ? 16 : 0;
            int bb    = (mg >= Nn) ? 1 : 0;
            const float* asrc = valid
                ? x + (size_t)bb * Cc * Nn + (size_t)(k0 + k) * Nn + (mg - bb * Nn)
                : x;
            cp_async16(abase + (uint32_t)(k * TSTRIDE + loc) * 4, asrc, valid);
            const float* bsrc = W + (size_t)(k0 + k) * OUT + loc;
            cp_async16(bbase + (uint32_t)(k * TSTRIDE + loc) * 4, bsrc, 16);
        }
        cp_commit();
    };

    stage_copy(0);
    stage_copy(1);

    for (int s = 0; s < KSTAGES; s++) {
        if (s < KSTAGES - 1) cp_wait<1>(); else cp_wait<0>();
        __syncthreads();
        if (s + 2 < KSTAGES) stage_copy(s + 2);

        const uint32_t* A  = smem_dyn + (size_t)(s % NBUF) * 2 * TILE_WORDS;
        const uint32_t* Bt = A + TILE_WORDS;

        #pragma unroll
        for (int kk = 0; kk < 4; kk++) {
            int kb = kk * 8;
            uint32_t af[2][4];
            #pragma unroll
            for (int mt = 0; mt < 2; mt++) {
                int r = wm * 32 + mt * 16 + lrow;
                af[mt][0] = A[(kb + lcol) * TSTRIDE + r];
                af[mt][1] = A[(kb + lcol) * TSTRIDE + r + 8];
                af[mt][2] = A[(kb + lcol + 4) * TSTRIDE + r];
                af[mt][3] = A[(kb + lcol + 4) * TSTRIDE + r + 8];
            }
            #pragma unroll
            for (int nt = 0; nt < 8; nt++) {
                int cn = wn * 64 + nt * 8 + lrow;
                uint32_t b0 = Bt[(kb + lcol) * TSTRIDE + cn];
                uint32_t b1 = Bt[(kb + lcol + 4) * TSTRIDE + cn];
                #pragma unroll
                for (int mt = 0; mt < 2; mt++) {
                    asm volatile(
                        "mma.sync.aligned.m16n8k8.row.col.f32.tf32.tf32.f32 "
                        "{%0,%1,%2,%3}, {%4,%5,%6,%7}, {%8,%9}, {%0,%1,%2,%3};\n"
                        : "+f"(acc[mt][nt][0]), "+f"(acc[mt][nt][1]),
                          "+f"(acc[mt][nt][2]), "+f"(acc[mt][nt][3])
                        : "r"(af[mt][0]), "r"(af[mt][1]), "r"(af[mt][2]), "r"(af[mt][3]),
                          "r"(b0), "r"(b1));
                }
            }
        }
    }

    #pragma unroll
    for (int mt = 0; mt < 2; mt++) {
        #pragma unroll
        for (int nt = 0; nt < 8; nt++) {
            int row = m0 + wm * 32 + mt * 16 + lrow;
            int col = wn * 64 + nt * 8 + lcol * 2;
            float bcol0 = bias[col], bcol1 = bias[col + 1];
            if (row < Mm) {
                float2 v = {acc[mt][nt][0] + bcol0, acc[mt][nt][1] + bcol1};
                *(float2*)&h[(size_t)row * OUT + col] = v;
            }
            if (row + 8 < Mm) {
                float2 v = {acc[mt][nt][2] + bcol0, acc[mt][nt][3] + bcol1};
                *(float2*)&h[(size_t)(row + 8) * OUT + col] = v;
            }
        }
    }
}

// ---- gather helper: logit partial over this lane's 4 features ----
__device__ __forceinline__ float edge_logit(const float4& l, const float4& hr,
                                            const float4& a) {
    float ex = l.x + hr.x, ey = l.y + hr.y, ez = l.z + hr.z, ew = l.w + hr.w;
    ex = ex > 0.f ? ex : NEG_SLOPE_GAT * ex;
    ey = ey > 0.f ? ey : NEG_SLOPE_GAT * ey;
    ez = ez > 0.f ? ez : NEG_SLOPE_GAT * ez;
    ew = ew > 0.f ? ew : NEG_SLOPE_GAT * ew;
    return ex * a.x + ey * a.y + ez * a.z + ew * a.w;
}

// ---- K_GATHER: fused scoring + exp-sum aggregation + bias + LN + LeakyReLU ----
// One warp per dst node. Lanes 0-15: head 0, 16-31: head 1 (4 features/lane).
// Unroll-2 into a SINGLE accumulator set (no max bookkeeping -> plain sums);
// min-blocks 6 caps registers at 42 for ~75% theoretical occupancy.
__global__ void __launch_bounds__(256, 6)
k_gather(float* __restrict__ out, const float* __restrict__ att,
         const float* __restrict__ bias,
         const float* __restrict__ gamma, const float* __restrict__ beta) {
    int gid  = blockIdx.x * blockDim.x + threadIdx.x;
    int m    = gid >> 5;
    int lane = threadIdx.x & 31;
    if (m >= Mm) return;
    int start = g_rowptr[m];
    int deg   = g_rowptr[m + 1] - start;

    const float4 hr4 = *(const float4*)(g_hr + (size_t)m * OUT + lane * 4);
    const float4 a4  = *(const float4*)(att + lane * 4);

    float den = 0.f, ac0 = 0.f, ac1 = 0.f, ac2 = 0.f, ac3 = 0.f;

    for (int base = 0; base < deg; base += 32) {
        int nb = deg - base; if (nb > 32) nb = 32;
        int sidx = g_csr_src[start + base + ((lane < nb) ? lane : 0)];
        int jj = 0;
        for (; jj + 2 <= nb; jj += 2) {
            int s0 = __shfl_sync(0xFFFFFFFFu, sidx, jj);
            int s1 = __shfl_sync(0xFFFFFFFFu, sidx, jj + 1);
            const float4 l0 = *(const float4*)(g_hl + (size_t)s0 * OUT + lane * 4);
            const float4 l1 = *(const float4*)(g_hl + (size_t)s1 * OUT + lane * 4);
            float p0 = edge_logit(l0, hr4, a4);
            float p1 = edge_logit(l1, hr4, a4);
            #pragma unroll
            for (int off = 8; off > 0; off >>= 1) {
                p0 += __shfl_xor_sync(0xFFFFFFFFu, p0, off);
                p1 += __shfl_xor_sync(0xFFFFFFFFu, p1, off);
            }
            float w0 = __expf(p0);
            float w1 = __expf(p1);
            den += w0;        den += w1;
            ac0 += w0 * l0.x; ac0 += w1 * l1.x;
            ac1 += w0 * l0.y; ac1 += w1 * l1.y;
            ac2 += w0 * l0.z; ac2 += w1 * l1.z;
            ac3 += w0 * l0.w; ac3 += w1 * l1.w;
        }
        if (jj < nb) {
            int s0 = __shfl_sync(0xFFFFFFFFu, sidx, jj);
            const float4 l0 = *(const float4*)(g_hl + (size_t)s0 * OUT + lane * 4);
            float p0 = edge_logit(l0, hr4, a4);
            #pragma unroll
            for (int off = 8; off > 0; off >>= 1)
                p0 += __shfl_xor_sync(0xFFFFFFFFu, p0, off);
            float w0 = __expf(p0);
            den += w0;
            ac0 += w0 * l0.x;
            ac1 += w0 * l0.y;
            ac2 += w0 * l0.z;
            ac3 += w0 * l0.w;
        }
    }

    float inv_d = 1.f / (den + SOFTMAX_EPS);
    const float4 b4 = *(const float4*)(bias + lane * 4);
    float v0 = ac0 * inv_d + b4.x;
    float v1 = ac1 * inv_d + b4.y;
    float v2 = ac2 * inv_d + b4.z;
    float v3 = ac3 * inv_d + b4.w;

    float s  = v0 + v1 + v2 + v3;
    float s2 = v0 * v0 + v1 * v1 + v2 * v2 + v3 * v3;
    #pragma unroll
    for (int off = 16; off > 0; off >>= 1) {
        s  += __shfl_xor_sync(0xFFFFFFFFu, s,  off);
        s2 += __shfl_xor_sync(0xFFFFFFFFu, s2, off);
    }
    float mu  = s * (1.f / OUT);
    float var = s2 * (1.f / OUT) - mu * mu;
    float inv = rsqrtf(var + LN_EPS);

    const float4 g4 = *(const float4*)(gamma + lane * 4);
    const float4 t4 = *(const float4*)(beta + lane * 4);
    float4 y;
    y.x = (v0 - mu) * inv * g4.x + t4.x;
    y.y = (v1 - mu) * inv * g4.y + t4.y;
    y.z = (v2 - mu) * inv * g4.z + t4.z;
    y.w = (v3 - mu) * inv * g4.w + t4.w;
    y.x = y.x > 0.f ? y.x : NEG_SLOPE_ACT * y.x;
    y.y = y.y > 0.f ? y.y : NEG_SLOPE_ACT * y.y;
    y.z = y.z > 0.f ? y.z : NEG_SLOPE_ACT * y.z;
    y.w = y.w > 0.f ? y.w : NEG_SLOPE_ACT * y.w;
    *(float4*)(out + (size_t)m * OUT + lane * 4) = y;
}

extern "C" void kernel_launch(void* const* d_in, const int* in_sizes, int n_in,
                              void* d_out, int out_size) {
    const float* x        = (const float*)d_in[0];
    const int*   ei       = (const int*)  d_in[1];
    const float* Wl       = (const float*)d_in[2];
    const float* bl       = (const float*)d_in[3];
    const float* Wr       = (const float*)d_in[4];
    const float* br       = (const float*)d_in[5];
    const float* att      = (const float*)d_in[6];
    const float* bias_gat = (const float*)d_in[7];
    const float* gamma    = (const float*)d_in[8];
    const float* beta     = (const float*)d_in[9];
    float* out = (float*)d_out;

    (void)in_sizes; (void)n_in; (void)out_size;

    // 4 launches, serial on stream 0. k_gather is launch #4 (profiled).
    k_csr_a  <<<CSR_BLOCKS, CSR_T>>>(ei);                     // launch #1
    k_scatter<<<(Ee / 4 + 255) / 256, 256>>>(ei);             // launch #2

    dim3 ggrid(2, (Mm + BM - 1) / BM);
    k_gemm_tc<<<ggrid, 256, GEMM_SMEM>>>(x, Wl, bl, Wr, br);  // launch #3

    k_gather<<<(Mm * 32 + 255) / 256, 256>>>(out, att, bias_gat, gamma, beta); // #4
}